// round 2
// baseline (speedup 1.0000x reference)
#include <cuda_runtime.h>
#include <math.h>

#define BATCH 16
#define SEQN  8256
#define CTX   8192
#define LAT   64
#define DIMM  512
#define NHEAD 8
#define HDIM  64

// Scratch (allocation-free rule: __device__ globals)
__device__ float g_kv[(size_t)BATCH * SEQN * DIMM];  // raw kv projection (rope applied later)
__device__ float g_q[BATCH * LAT * DIMM];            // raw q projection (latent rows only)
__device__ float g_cos[SEQN * 32];
__device__ float g_sin[SEQN * 32];

// ---------------------------------------------------------------------------
// Rope table: cos/sin(j * inv_freq[k]) for j in [0,8256), k in [0,32)
// ---------------------------------------------------------------------------
__global__ void rope_table_kernel() {
    int idx = blockIdx.x * blockDim.x + threadIdx.x;
    if (idx >= SEQN * 32) return;
    int j = idx >> 5, k = idx & 31;
    double inv = exp(-((double)(2 * k) / 64.0) * log(10000.0));
    float ang = (float)j * (float)inv;   // fp32 multiply, matches reference
    g_cos[idx] = cosf(ang);
    g_sin[idx] = sinf(ang);
}

// ---------------------------------------------------------------------------
// C[m][n] = sum_k A[m][k] * W[n][k]    (A @ W^T)
// BM=128, BN=128, BK=16, 256 threads, 8x8 microtile, reg-staged double buffer.
// latent=1: A rows remapped to the last 64 positions per batch; C = g_q.
// ---------------------------------------------------------------------------
__global__ __launch_bounds__(256) void gemm_proj(const float* __restrict__ A,
                                                 const float* __restrict__ W,
                                                 int latent) {
    __shared__ float As[2][16][128];
    __shared__ float Bs[2][16][128];
    float* C = latent ? g_q : g_kv;

    int tid = threadIdx.x;
    int ty = tid >> 4, tx = tid & 15;
    int m0 = blockIdx.x * 128, n0 = blockIdx.y * 128;

    const float* aptr[2];
    const float* bptr[2];
#pragma unroll
    for (int t = 0; t < 2; t++) {
        int idx = tid * 2 + t;
        int r = idx >> 2, c4 = idx & 3;
        int row = m0 + r;
        if (latent) row = (row >> 6) * SEQN + CTX + (row & 63);
        aptr[t] = A + (size_t)row * DIMM + c4 * 4;
        bptr[t] = W + (size_t)(n0 + r) * DIMM + c4 * 4;
    }

    float acc[8][8];
#pragma unroll
    for (int i = 0; i < 8; i++)
#pragma unroll
        for (int j = 0; j < 8; j++) acc[i][j] = 0.f;

    float4 aReg[2], bReg[2];
#pragma unroll
    for (int t = 0; t < 2; t++) {
        aReg[t] = *(const float4*)(aptr[t]);
        bReg[t] = *(const float4*)(bptr[t]);
    }
#pragma unroll
    for (int t = 0; t < 2; t++) {
        int idx = tid * 2 + t;
        int r = idx >> 2, c4 = idx & 3;
        As[0][c4 * 4 + 0][r] = aReg[t].x; As[0][c4 * 4 + 1][r] = aReg[t].y;
        As[0][c4 * 4 + 2][r] = aReg[t].z; As[0][c4 * 4 + 3][r] = aReg[t].w;
        Bs[0][c4 * 4 + 0][r] = bReg[t].x; Bs[0][c4 * 4 + 1][r] = bReg[t].y;
        Bs[0][c4 * 4 + 2][r] = bReg[t].z; Bs[0][c4 * 4 + 3][r] = bReg[t].w;
    }
    __syncthreads();

#pragma unroll 1
    for (int kt = 0; kt < DIMM / 16; kt++) {
        int cur = kt & 1;
        if (kt < DIMM / 16 - 1) {
            int k0 = (kt + 1) * 16;
#pragma unroll
            for (int t = 0; t < 2; t++) {
                aReg[t] = *(const float4*)(aptr[t] + k0);
                bReg[t] = *(const float4*)(bptr[t] + k0);
            }
        }
#pragma unroll
        for (int kk = 0; kk < 16; kk++) {
            float4 a0 = *(const float4*)&As[cur][kk][ty * 8];
            float4 a1 = *(const float4*)&As[cur][kk][ty * 8 + 4];
            float4 b0 = *(const float4*)&Bs[cur][kk][tx * 8];
            float4 b1 = *(const float4*)&Bs[cur][kk][tx * 8 + 4];
            float ar[8] = {a0.x, a0.y, a0.z, a0.w, a1.x, a1.y, a1.z, a1.w};
            float br[8] = {b0.x, b0.y, b0.z, b0.w, b1.x, b1.y, b1.z, b1.w};
#pragma unroll
            for (int i = 0; i < 8; i++)
#pragma unroll
                for (int j = 0; j < 8; j++) acc[i][j] += ar[i] * br[j];
        }
        if (kt < DIMM / 16 - 1) {
            int nxt = cur ^ 1;
#pragma unroll
            for (int t = 0; t < 2; t++) {
                int idx = tid * 2 + t;
                int r = idx >> 2, c4 = idx & 3;
                As[nxt][c4 * 4 + 0][r] = aReg[t].x; As[nxt][c4 * 4 + 1][r] = aReg[t].y;
                As[nxt][c4 * 4 + 2][r] = aReg[t].z; As[nxt][c4 * 4 + 3][r] = aReg[t].w;
                Bs[nxt][c4 * 4 + 0][r] = bReg[t].x; Bs[nxt][c4 * 4 + 1][r] = bReg[t].y;
                Bs[nxt][c4 * 4 + 2][r] = bReg[t].z; Bs[nxt][c4 * 4 + 3][r] = bReg[t].w;
            }
        }
        __syncthreads();
    }

#pragma unroll
    for (int i = 0; i < 8; i++) {
        size_t row = (size_t)m0 + ty * 8 + i;
        float4 w0 = {acc[i][0], acc[i][1], acc[i][2], acc[i][3]};
        float4 w1 = {acc[i][4], acc[i][5], acc[i][6], acc[i][7]};
        *(float4*)&C[row * DIMM + n0 + tx * 8]     = w0;
        *(float4*)&C[row * DIMM + n0 + tx * 8 + 4] = w1;
    }
}

// ---------------------------------------------------------------------------
// Fused attention: one CTA per (b, h). Per 64-key tile: load raw kv, apply
// RoPE, compute LN(kv) on the fly, online softmax, accumulate P@LKV.
// ---------------------------------------------------------------------------
__global__ __launch_bounds__(256) void attn_kernel(const float* __restrict__ lng,
                                                   const float* __restrict__ lnb,
                                                   float* __restrict__ out) {
    extern __shared__ float sm[];
    float* qT  = sm;                  // [64][64]  dd-major: qT[dd*64+qi]
    float* kvT = sm + 4096;           // [64][64]  dd-major: roped kv
    float* lkv = sm + 8192;           // [64][68]  kj-major: staging raw -> LN'ed kv
    float* Pt  = sm + 8192 + 64 * 68; // [64][68]  kj-major: probabilities [kj][qi]
    float* gS  = Pt + 64 * 68;        // ln gamma (64)
    float* bS  = gS + 64;             // ln beta  (64)

    int tid = threadIdx.x;
    int bh = blockIdx.x;
    int b = bh >> 3, h = bh & 7;
    int ty = tid >> 4, tx = tid & 15;

    if (tid < 64) { gS[tid] = lng[tid]; bS[tid] = lnb[tid]; }

    // ---- q tile: load raw, rope (pos = CTX+qi), scale, store transposed
#pragma unroll
    for (int t = 0; t < 4; t++) {
        int idx = tid + t * 256;
        int r = idx >> 4, c4 = idx & 15;
        *(float4*)&lkv[r * 68 + c4 * 4] =
            *(const float4*)&g_q[((size_t)(b * LAT + r)) * DIMM + h * HDIM + c4 * 4];
    }
    __syncthreads();
    {
        int qi = tid >> 2, qq = tid & 3;
        float raw[16], rawp[16];
#pragma unroll
        for (int i = 0; i < 16; i++) {
            int dd = qq * 16 + i;
            raw[i]  = lkv[qi * 68 + dd];
            rawp[i] = lkv[qi * 68 + (dd ^ 32)];
        }
        __syncwarp();
        int pos = CTX + qi;
#pragma unroll
        for (int i = 0; i < 16; i++) {
            int dd = qq * 16 + i;
            float c = g_cos[pos * 32 + (dd & 31)];
            float s = g_sin[pos * 32 + (dd & 31)];
            float rot = (dd < 32) ? -rawp[i] : rawp[i];
            qT[dd * 64 + qi] = (raw[i] * c + rot * s) * 0.125f;  // * d^-0.5
        }
    }
    __syncthreads();

    float m[4], l[4], o[4][4];
#pragma unroll
    for (int u = 0; u < 4; u++) {
        m[u] = -1e30f; l[u] = 0.f;
#pragma unroll
        for (int v = 0; v < 4; v++) o[u][v] = 0.f;
    }

    for (int jt = 0; jt < SEQN / 64; jt++) {
        int j0 = jt * 64;
        // load raw kv tile
#pragma unroll
        for (int t = 0; t < 4; t++) {
            int idx = tid + t * 256;
            int r = idx >> 4, c4 = idx & 15;
            *(float4*)&lkv[r * 68 + c4 * 4] =
                *(const float4*)&g_kv[((size_t)b * SEQN + j0 + r) * DIMM + h * HDIM + c4 * 4];
        }
        __syncthreads();
        // rope + layernorm
        {
            int kj = tid >> 2, qq = tid & 3;
            int j = j0 + kj;
            float raw[16], rawp[16];
#pragma unroll
            for (int i = 0; i < 16; i++) {
                int dd = qq * 16 + i;
                raw[i]  = lkv[kj * 68 + dd];
                rawp[i] = lkv[kj * 68 + (dd ^ 32)];
            }
            __syncwarp();
            float rv[16], s1 = 0.f, s2 = 0.f;
#pragma unroll
            for (int i = 0; i < 16; i++) {
                int dd = qq * 16 + i;
                float c = g_cos[j * 32 + (dd & 31)];
                float s = g_sin[j * 32 + (dd & 31)];
                float rot = (dd < 32) ? -rawp[i] : rawp[i];
                float v = raw[i] * c + rot * s;
                rv[i] = v;
                kvT[dd * 64 + kj] = v;
                s1 += v; s2 += v * v;
            }
            s1 += __shfl_xor_sync(0xffffffffu, s1, 1);
            s1 += __shfl_xor_sync(0xffffffffu, s1, 2);
            s2 += __shfl_xor_sync(0xffffffffu, s2, 1);
            s2 += __shfl_xor_sync(0xffffffffu, s2, 2);
            float mu = s1 * (1.f / 64.f);
            float var = s2 * (1.f / 64.f) - mu * mu;
            float rstd = rsqrtf(var + 1e-5f);
#pragma unroll
            for (int i = 0; i < 16; i++) {
                int dd = qq * 16 + i;
                lkv[kj * 68 + dd] = (rv[i] - mu) * rstd * gS[dd] + bS[dd];
            }
        }
        __syncthreads();

        // scores S = Q @ KV^T  (64q x 64k, 4x4 per thread)
        float S[4][4];
#pragma unroll
        for (int u = 0; u < 4; u++)
#pragma unroll
            for (int v = 0; v < 4; v++) S[u][v] = 0.f;
#pragma unroll 8
        for (int dd = 0; dd < 64; dd++) {
            float4 qa = *(const float4*)&qT[dd * 64 + ty * 4];
            float4 kb = *(const float4*)&kvT[dd * 64 + tx * 4];
            float qv[4] = {qa.x, qa.y, qa.z, qa.w};
            float kv4[4] = {kb.x, kb.y, kb.z, kb.w};
#pragma unroll
            for (int u = 0; u < 4; u++)
#pragma unroll
                for (int v = 0; v < 4; v++) S[u][v] += qv[u] * kv4[v];
        }

        // online softmax
        float pbuf[4][4];
#pragma unroll
        for (int u = 0; u < 4; u++) {
            float tm = fmaxf(fmaxf(S[u][0], S[u][1]), fmaxf(S[u][2], S[u][3]));
            tm = fmaxf(tm, __shfl_xor_sync(0xffffffffu, tm, 1));
            tm = fmaxf(tm, __shfl_xor_sync(0xffffffffu, tm, 2));
            tm = fmaxf(tm, __shfl_xor_sync(0xffffffffu, tm, 4));
            tm = fmaxf(tm, __shfl_xor_sync(0xffffffffu, tm, 8));
            float mn = fmaxf(m[u], tm);
            float corr = __expf(m[u] - mn);
            m[u] = mn;
            float ps = 0.f;
#pragma unroll
            for (int v = 0; v < 4; v++) {
                float p = __expf(S[u][v] - mn);
                pbuf[u][v] = p; ps += p;
            }
            ps += __shfl_xor_sync(0xffffffffu, ps, 1);
            ps += __shfl_xor_sync(0xffffffffu, ps, 2);
            ps += __shfl_xor_sync(0xffffffffu, ps, 4);
            ps += __shfl_xor_sync(0xffffffffu, ps, 8);
            l[u] = l[u] * corr + ps;
#pragma unroll
            for (int v = 0; v < 4; v++) o[u][v] *= corr;
        }
#pragma unroll
        for (int v = 0; v < 4; v++) {
            float4 w = {pbuf[0][v], pbuf[1][v], pbuf[2][v], pbuf[3][v]};
            *(float4*)&Pt[(tx * 4 + v) * 68 + ty * 4] = w;
        }
        __syncthreads();

        // out += P @ LKV
#pragma unroll 8
        for (int kj = 0; kj < 64; kj++) {
            float4 pp = *(const float4*)&Pt[kj * 68 + ty * 4];
            float4 lv = *(const float4*)&lkv[kj * 68 + tx * 4];
            float pv4[4] = {pp.x, pp.y, pp.z, pp.w};
            float lv4[4] = {lv.x, lv.y, lv.z, lv.w};
#pragma unroll
            for (int u = 0; u < 4; u++)
#pragma unroll
                for (int v = 0; v < 4; v++) o[u][v] += pv4[u] * lv4[v];
        }
        __syncthreads();
    }

    // epilogue: divide by l, write out[b, qi, h*64 + dd]
#pragma unroll
    for (int u = 0; u < 4; u++) {
        float inv = 1.f / l[u];
        int qi = ty * 4 + u;
        float4 w = {o[u][0] * inv, o[u][1] * inv, o[u][2] * inv, o[u][3] * inv};
        *(float4*)&out[((size_t)(b * LAT + qi)) * DIMM + h * HDIM + tx * 4] = w;
    }
}

extern "C" void kernel_launch(void* const* d_in, const int* in_sizes, int n_in,
                              void* d_out, int out_size) {
    (void)in_sizes; (void)n_in; (void)out_size;
    const float* x   = (const float*)d_in[0];
    const float* wq  = (const float*)d_in[1];
    const float* wkv = (const float*)d_in[2];
    const float* lng = (const float*)d_in[3];
    const float* lnb = (const float*)d_in[4];
    float* out = (float*)d_out;

    int smem_bytes = (8192 + 2 * 64 * 68 + 128) * 4;  // 68096 B
    cudaFuncSetAttribute(attn_kernel, cudaFuncAttributeMaxDynamicSharedMemorySize,
                         smem_bytes);

    rope_table_kernel<<<(SEQN * 32 + 255) / 256, 256>>>();
    gemm_proj<<<dim3((BATCH * SEQN) / 128, DIMM / 128), 256>>>(x, wkv, 0);
    gemm_proj<<<dim3((BATCH * LAT) / 128, DIMM / 128), 256>>>(x, wq, 1);
    attn_kernel<<<BATCH * NHEAD, 256, smem_bytes>>>(lng, lnb, out);
}

// round 17
// speedup vs baseline: 1.7105x; 1.7105x over previous
#include <cuda_runtime.h>
#include <cuda_bf16.h>
#include <math.h>
#include <stdint.h>

#define BATCH 16
#define SEQN  8256
#define CTX   8192
#define LAT   64
#define DIMM  512
#define NHEAD 8
#define HDIM  64
#define MROWS (BATCH * SEQN)   // 132096
#define NSPLIT 4
#define NTILES (SEQN / 64)     // 129

// ---------------- scratch (__device__ globals; no allocations) --------------
__device__ float g_kv[(size_t)MROWS * DIMM];
__device__ float g_q[BATCH * LAT * DIMM];
__device__ float g_cos[SEQN * 32];
__device__ float g_sin[SEQN * 32];
__device__ __nv_bfloat16 g_xhi[(size_t)MROWS * DIMM];
__device__ __nv_bfloat16 g_xlo[(size_t)MROWS * DIMM];
__device__ __nv_bfloat16 g_wqhi[DIMM * DIMM];
__device__ __nv_bfloat16 g_wqlo[DIMM * DIMM];
__device__ __nv_bfloat16 g_wkhi[DIMM * DIMM];
__device__ __nv_bfloat16 g_wklo[DIMM * DIMM];
// split-KV partials
__device__ float g_pm[BATCH * NHEAD * NSPLIT * LAT];
__device__ float g_pl[BATCH * NHEAD * NSPLIT * LAT];
__device__ float g_po[(size_t)BATCH * NHEAD * NSPLIT * LAT * HDIM];

// ---------------- helpers (sm_80-era features only; NO tcgen05) -------------
__device__ __forceinline__ uint32_t smem_u32(const void* p) {
    uint32_t a;
    asm("{ .reg .u64 t; cvta.to.shared.u64 t, %1; cvt.u32.u64 %0, t; }"
        : "=r"(a) : "l"(p));
    return a;
}
__device__ __forceinline__ void cp_async16(uint32_t dst, const void* src) {
    asm volatile("cp.async.cg.shared.global [%0], [%1], 16;"
                 :: "r"(dst), "l"(src));
}
#define CP_COMMIT() asm volatile("cp.async.commit_group;" ::: "memory")
#define CP_WAIT(n)  asm volatile("cp.async.wait_group %0;" :: "n"(n) : "memory")

__device__ __forceinline__ void ldsm_x4(uint32_t* r, uint32_t addr) {
    asm volatile("ldmatrix.sync.aligned.m8n8.x4.shared.b16 {%0,%1,%2,%3}, [%4];"
                 : "=r"(r[0]), "=r"(r[1]), "=r"(r[2]), "=r"(r[3]) : "r"(addr));
}
__device__ __forceinline__ void mma16816(float* d, const uint32_t* a,
                                         uint32_t b0, uint32_t b1) {
    asm volatile(
        "mma.sync.aligned.m16n8k16.row.col.f32.bf16.bf16.f32 "
        "{%0,%1,%2,%3}, {%4,%5,%6,%7}, {%8,%9}, {%0,%1,%2,%3};"
        : "+f"(d[0]), "+f"(d[1]), "+f"(d[2]), "+f"(d[3])
        : "r"(a[0]), "r"(a[1]), "r"(a[2]), "r"(a[3]), "r"(b0), "r"(b1));
}

// SW64 swizzle for 64-byte rows (conflict-free ldmatrix on [row][32 bf16])
#define SWZ64(x) ((x) ^ (((x) >> 3) & 0x30))

// ---------------------------------------------------------------------------
// split fp32 -> bf16 hi + bf16 lo
// ---------------------------------------------------------------------------
__global__ void split_kernel(const float* __restrict__ src,
                             __nv_bfloat16* __restrict__ hi,
                             __nv_bfloat16* __restrict__ lo, int n4) {
    int i = blockIdx.x * blockDim.x + threadIdx.x;
    if (i >= n4) return;
    float4 v = ((const float4*)src)[i];
    __nv_bfloat16 h0 = __float2bfloat16(v.x), h1 = __float2bfloat16(v.y);
    __nv_bfloat16 h2 = __float2bfloat16(v.z), h3 = __float2bfloat16(v.w);
    __nv_bfloat16 l0 = __float2bfloat16(v.x - __bfloat162float(h0));
    __nv_bfloat16 l1 = __float2bfloat16(v.y - __bfloat162float(h1));
    __nv_bfloat16 l2 = __float2bfloat16(v.z - __bfloat162float(h2));
    __nv_bfloat16 l3 = __float2bfloat16(v.w - __bfloat162float(h3));
    ((__nv_bfloat162*)hi)[i * 2]     = __nv_bfloat162(h0, h1);
    ((__nv_bfloat162*)hi)[i * 2 + 1] = __nv_bfloat162(h2, h3);
    ((__nv_bfloat162*)lo)[i * 2]     = __nv_bfloat162(l0, l1);
    ((__nv_bfloat162*)lo)[i * 2 + 1] = __nv_bfloat162(l2, l3);
}

// ---------------------------------------------------------------------------
// rope table
// ---------------------------------------------------------------------------
__global__ void rope_table_kernel() {
    int idx = blockIdx.x * blockDim.x + threadIdx.x;
    if (idx >= SEQN * 32) return;
    int j = idx >> 5, k = idx & 31;
    double inv = exp(-((double)(2 * k) / 64.0) * log(10000.0));
    float ang = (float)j * (float)inv;
    g_cos[idx] = cosf(ang);
    g_sin[idx] = sinf(ang);
}

// ---------------------------------------------------------------------------
// mma.sync bf16 GEMM: C = A @ W^T via 3-pass hi/lo split.
// CTA tile 128x128, BK=32, 4-stage cp.async pipeline, 8 warps (warp tile 32x64).
// Accumulators live in registers across all 48 K-chunks (3 passes x 16).
// ---------------------------------------------------------------------------
#define GSTAGES 4
#define STAGE_BYTES 16384   // A 8KB + B 8KB

__global__ __launch_bounds__(256) void gemm_mma(int latent) {
    extern __shared__ __align__(128) char smem[];
    uint32_t sbase = smem_u32(smem);

    int tid = threadIdx.x;
    int wid = tid >> 5, lid = tid & 31;
    int m0 = blockIdx.x * 128, n0 = blockIdx.y * 128;
    int warp_m = (wid & 3) * 32;   // 4 warps over M (32 rows each)
    int warp_n = (wid >> 2) * 64;  // 2 warps over N (64 cols each)

    const __nv_bfloat16* axhi = g_xhi;
    const __nv_bfloat16* axlo = g_xlo;
    const __nv_bfloat16* bwhi = latent ? g_wqhi : g_wkhi;
    const __nv_bfloat16* bwlo = latent ? g_wqlo : g_wklo;
    float* C = latent ? g_q : g_kv;

    // per-thread load slots: 4 x 16B chunks (A: 512 chunks, B: 512 chunks)
    size_t grow[4];
    uint32_t soff[4];
    int isA[4];
#pragma unroll
    for (int t = 0; t < 4; t++) {
        int chunk = tid + t * 256;        // 0..1023
        int arr = chunk >> 9;             // 0 = A, 1 = B
        int idx = chunk & 511;
        int row = idx >> 2, c16 = idx & 3;
        int rg = arr ? (n0 + row) : (m0 + row);
        if (!arr && latent) rg = (rg >> 6) * SEQN + CTX + (rg & 63);
        grow[t] = (size_t)rg * DIMM + c16 * 8;
        soff[t] = arr * 8192 + SWZ64(row * 64 + c16 * 16);
        isA[t] = !arr;
    }

    auto load_stage = [&](int kt) {
        int p = kt >> 4, kc = kt & 15;
        const __nv_bfloat16* Aarr = (p == 1) ? axlo : axhi;
        const __nv_bfloat16* Barr = (p == 2) ? bwlo : bwhi;
        int kbase = kc * 32;
        uint32_t sb = sbase + (kt & (GSTAGES - 1)) * STAGE_BYTES;
#pragma unroll
        for (int t = 0; t < 4; t++) {
            const __nv_bfloat16* src = (isA[t] ? Aarr : Barr) + grow[t] + kbase;
            cp_async16(sb + soff[t], src);
        }
        CP_COMMIT();
    };

    float acc[2][8][4];
#pragma unroll
    for (int am = 0; am < 2; am++)
#pragma unroll
        for (int bn = 0; bn < 8; bn++)
#pragma unroll
            for (int i = 0; i < 4; i++) acc[am][bn][i] = 0.f;

    load_stage(0);
    load_stage(1);
    load_stage(2);

    int lrow = lid & 15;          // ldmatrix row within 16
    int lcol = (lid >> 4) * 16;   // k-half byte offset (8 bf16 = 16B)

#pragma unroll 1
    for (int kt = 0; kt < 48; kt++) {
        CP_WAIT(2);
        __syncthreads();
        uint32_t ab = sbase + (kt & (GSTAGES - 1)) * STAGE_BYTES;
        uint32_t bb = ab + 8192;

#pragma unroll
        for (int kk = 0; kk < 2; kk++) {
            uint32_t afr[2][4], bfr[4][4];
#pragma unroll
            for (int am = 0; am < 2; am++) {
                uint32_t byte = (warp_m + am * 16 + lrow) * 64 + kk * 32 + lcol;
                ldsm_x4(afr[am], ab + SWZ64(byte));
            }
#pragma unroll
            for (int g = 0; g < 4; g++) {
                uint32_t byte = (warp_n + g * 16 + lrow) * 64 + kk * 32 + lcol;
                ldsm_x4(bfr[g], bb + SWZ64(byte));
            }
#pragma unroll
            for (int am = 0; am < 2; am++)
#pragma unroll
                for (int bn = 0; bn < 8; bn++) {
                    int g = bn >> 1, hf = bn & 1;
                    mma16816(acc[am][bn], afr[am], bfr[g][hf], bfr[g][2 + hf]);
                }
        }
        if (kt + 3 < 48) load_stage(kt + 3);
        else CP_COMMIT();   // empty group keeps wait_group bookkeeping uniform
    }

    // epilogue: write C (thread t owns rows m+t/4 and m+8+t/4, cols 2*(t%4)+{0,1})
    int erow = lid >> 2, ecol = (lid & 3) * 2;
#pragma unroll
    for (int am = 0; am < 2; am++) {
#pragma unroll
        for (int bn = 0; bn < 8; bn++) {
            int m = m0 + warp_m + am * 16 + erow;
            int n = n0 + warp_n + bn * 8 + ecol;
            float2 w0 = {acc[am][bn][0], acc[am][bn][1]};
            float2 w1 = {acc[am][bn][2], acc[am][bn][3]};
            *(float2*)&C[(size_t)m * DIMM + n] = w0;
            *(float2*)&C[(size_t)(m + 8) * DIMM + n] = w1;
        }
    }
}

// ---------------------------------------------------------------------------
// Split-KV fused attention: grid (128 bh, NSPLIT); partials to global scratch.
// ---------------------------------------------------------------------------
__global__ __launch_bounds__(256) void attn_split_kernel(const float* __restrict__ lng,
                                                         const float* __restrict__ lnb) {
    extern __shared__ float sm[];
    float* qT  = sm;
    float* kvT = sm + 4096;
    float* lkv = sm + 8192;
    float* Pt  = sm + 8192 + 64 * 68;
    float* gS  = Pt + 64 * 68;
    float* bS  = gS + 64;

    int tid = threadIdx.x;
    int bh = blockIdx.x;
    int sp = blockIdx.y;
    int b = bh >> 3, h = bh & 7;
    int ty = tid >> 4, tx = tid & 15;

    const int T0 = (NTILES + NSPLIT - 1) / NSPLIT;          // 33
    int t0 = sp * T0;
    int t1 = min(NTILES, t0 + T0);

    if (tid < 64) { gS[tid] = lng[tid]; bS[tid] = lnb[tid]; }

#pragma unroll
    for (int t = 0; t < 4; t++) {
        int idx = tid + t * 256;
        int r = idx >> 4, c4 = idx & 15;
        *(float4*)&lkv[r * 68 + c4 * 4] =
            *(const float4*)&g_q[((size_t)(b * LAT + r)) * DIMM + h * HDIM + c4 * 4];
    }
    __syncthreads();
    {
        int qi = tid >> 2, qq = tid & 3;
        float raw[16], rawp[16];
#pragma unroll
        for (int i = 0; i < 16; i++) {
            int dd = qq * 16 + i;
            raw[i]  = lkv[qi * 68 + dd];
            rawp[i] = lkv[qi * 68 + (dd ^ 32)];
        }
        __syncwarp();
        int pos = CTX + qi;
#pragma unroll
        for (int i = 0; i < 16; i++) {
            int dd = qq * 16 + i;
            float c = g_cos[pos * 32 + (dd & 31)];
            float s = g_sin[pos * 32 + (dd & 31)];
            float rot = (dd < 32) ? -rawp[i] : rawp[i];
            qT[dd * 64 + qi] = (raw[i] * c + rot * s) * 0.125f;
        }
    }
    __syncthreads();

    float m[4], l[4], o[4][4];
#pragma unroll
    for (int u = 0; u < 4; u++) {
        m[u] = -1e30f; l[u] = 0.f;
#pragma unroll
        for (int v = 0; v < 4; v++) o[u][v] = 0.f;
    }

    for (int jt = t0; jt < t1; jt++) {
        int j0 = jt * 64;
#pragma unroll
        for (int t = 0; t < 4; t++) {
            int idx = tid + t * 256;
            int r = idx >> 4, c4 = idx & 15;
            *(float4*)&lkv[r * 68 + c4 * 4] =
                *(const float4*)&g_kv[((size_t)b * SEQN + j0 + r) * DIMM + h * HDIM + c4 * 4];
        }
        __syncthreads();
        {
            int kj = tid >> 2, qq = tid & 3;
            int j = j0 + kj;
            float raw[16], rawp[16];
#pragma unroll
            for (int i = 0; i < 16; i++) {
                int dd = qq * 16 + i;
                raw[i]  = lkv[kj * 68 + dd];
                rawp[i] = lkv[kj * 68 + (dd ^ 32)];
            }
            __syncwarp();
            float rv[16], s1 = 0.f, s2 = 0.f;
#pragma unroll
            for (int i = 0; i < 16; i++) {
                int dd = qq * 16 + i;
                float c = g_cos[j * 32 + (dd & 31)];
                float s = g_sin[j * 32 + (dd & 31)];
                float rot = (dd < 32) ? -rawp[i] : rawp[i];
                float v = raw[i] * c + rot * s;
                rv[i] = v;
                kvT[dd * 64 + kj] = v;
                s1 += v; s2 += v * v;
            }
            s1 += __shfl_xor_sync(0xffffffffu, s1, 1);
            s1 += __shfl_xor_sync(0xffffffffu, s1, 2);
            s2 += __shfl_xor_sync(0xffffffffu, s2, 1);
            s2 += __shfl_xor_sync(0xffffffffu, s2, 2);
            float mu = s1 * (1.f / 64.f);
            float var = s2 * (1.f / 64.f) - mu * mu;
            float rstd = rsqrtf(var + 1e-5f);
#pragma unroll
            for (int i = 0; i < 16; i++) {
                int dd = qq * 16 + i;
                lkv[kj * 68 + dd] = (rv[i] - mu) * rstd * gS[dd] + bS[dd];
            }
        }
        __syncthreads();

        float S[4][4];
#pragma unroll
        for (int u = 0; u < 4; u++)
#pragma unroll
            for (int v = 0; v < 4; v++) S[u][v] = 0.f;
#pragma unroll 8
        for (int dd = 0; dd < 64; dd++) {
            float4 qa = *(const float4*)&qT[dd * 64 + ty * 4];
            float4 kb = *(const float4*)&kvT[dd * 64 + tx * 4];
            float qv[4] = {qa.x, qa.y, qa.z, qa.w};
            float kv4[4] = {kb.x, kb.y, kb.z, kb.w};
#pragma unroll
            for (int u = 0; u < 4; u++)
#pragma unroll
                for (int v = 0; v < 4; v++) S[u][v] += qv[u] * kv4[v];
        }

        float pbuf[4][4];
#pragma unroll
        for (int u = 0; u < 4; u++) {
            float tm = fmaxf(fmaxf(S[u][0], S[u][1]), fmaxf(S[u][2], S[u][3]));
            tm = fmaxf(tm, __shfl_xor_sync(0xffffffffu, tm, 1));
            tm = fmaxf(tm, __shfl_xor_sync(0xffffffffu, tm, 2));
            tm = fmaxf(tm, __shfl_xor_sync(0xffffffffu, tm, 4));
            tm = fmaxf(tm, __shfl_xor_sync(0xffffffffu, tm, 8));
            float mn = fmaxf(m[u], tm);
            float corr = __expf(m[u] - mn);
            m[u] = mn;
            float ps = 0.f;
#pragma unroll
            for (int v = 0; v < 4; v++) {
                float p = __expf(S[u][v] - mn);
                pbuf[u][v] = p; ps += p;
            }
            ps += __shfl_xor_sync(0xffffffffu, ps, 1);
            ps += __shfl_xor_sync(0xffffffffu, ps, 2);
            ps += __shfl_xor_sync(0xffffffffu, ps, 4);
            ps += __shfl_xor_sync(0xffffffffu, ps, 8);
            l[u] = l[u] * corr + ps;
#pragma unroll
            for (int v = 0; v < 4; v++) o[u][v] *= corr;
        }
#pragma unroll
        for (int v = 0; v < 4; v++) {
            float4 w = {pbuf[0][v], pbuf[1][v], pbuf[2][v], pbuf[3][v]};
            *(float4*)&Pt[(tx * 4 + v) * 68 + ty * 4] = w;
        }
        __syncthreads();

#pragma unroll 8
        for (int kj = 0; kj < 64; kj++) {
            float4 pp = *(const float4*)&Pt[kj * 68 + ty * 4];
            float4 lv = *(const float4*)&lkv[kj * 68 + tx * 4];
            float pv4[4] = {pp.x, pp.y, pp.z, pp.w};
            float lv4[4] = {lv.x, lv.y, lv.z, lv.w};
#pragma unroll
            for (int u = 0; u < 4; u++)
#pragma unroll
                for (int v = 0; v < 4; v++) o[u][v] += pv4[u] * lv4[v];
        }
        __syncthreads();
    }

    int base = (bh * NSPLIT + sp) * LAT;
#pragma unroll
    for (int u = 0; u < 4; u++) {
        int qi = ty * 4 + u;
        if (tx == 0) {
            g_pm[base + qi] = m[u];
            g_pl[base + qi] = l[u];
        }
        float4 w = {o[u][0], o[u][1], o[u][2], o[u][3]};
        *(float4*)&g_po[((size_t)(base + qi)) * HDIM + tx * 4] = w;
    }
}

// ---------------------------------------------------------------------------
// Combine partials: out[b, qi, h*64+dd]
// ---------------------------------------------------------------------------
__global__ __launch_bounds__(256) void combine_kernel(float* __restrict__ out) {
    int bh = blockIdx.x;
    int b = bh >> 3, h = bh & 7;
    int tid = threadIdx.x;
    int qi = tid >> 2, grp = tid & 3;

    int base = bh * NSPLIT * LAT;
    float mv[NSPLIT], lv[NSPLIT];
    float M = -1e30f;
#pragma unroll
    for (int s = 0; s < NSPLIT; s++) {
        mv[s] = g_pm[base + s * LAT + qi];
        M = fmaxf(M, mv[s]);
    }
    float L = 0.f;
#pragma unroll
    for (int s = 0; s < NSPLIT; s++) {
        lv[s] = __expf(mv[s] - M);
        L += lv[s] * g_pl[base + s * LAT + qi];
    }
    float inv = 1.f / L;

#pragma unroll
    for (int c = 0; c < 4; c++) {
        int dd = grp * 16 + c * 4;
        float4 acc = {0.f, 0.f, 0.f, 0.f};
#pragma unroll
        for (int s = 0; s < NSPLIT; s++) {
            float4 v = *(const float4*)&g_po[((size_t)(base + s * LAT + qi)) * HDIM + dd];
            acc.x += v.x * lv[s]; acc.y += v.y * lv[s];
            acc.z += v.z * lv[s]; acc.w += v.w * lv[s];
        }
        acc.x *= inv; acc.y *= inv; acc.z *= inv; acc.w *= inv;
        *(float4*)&out[((size_t)(b * LAT + qi)) * DIMM + h * HDIM + dd] = acc;
    }
}

// ---------------------------------------------------------------------------
extern "C" void kernel_launch(void* const* d_in, const int* in_sizes, int n_in,
                              void* d_out, int out_size) {
    (void)in_sizes; (void)n_in; (void)out_size;
    const float* x   = (const float*)d_in[0];
    const float* wq  = (const float*)d_in[1];
    const float* wkv = (const float*)d_in[2];
    const float* lng = (const float*)d_in[3];
    const float* lnb = (const float*)d_in[4];
    float* out = (float*)d_out;

    void *p_xhi, *p_xlo, *p_wqhi, *p_wqlo, *p_wkhi, *p_wklo;
    cudaGetSymbolAddress(&p_xhi, g_xhi);
    cudaGetSymbolAddress(&p_xlo, g_xlo);
    cudaGetSymbolAddress(&p_wqhi, g_wqhi);
    cudaGetSymbolAddress(&p_wqlo, g_wqlo);
    cudaGetSymbolAddress(&p_wkhi, g_wkhi);
    cudaGetSymbolAddress(&p_wklo, g_wklo);

    int attn_smem = (8192 + 2 * 64 * 68 + 128) * 4;  // 68096 B
    cudaFuncSetAttribute(attn_split_kernel,
                         cudaFuncAttributeMaxDynamicSharedMemorySize, attn_smem);
    int gemm_smem = GSTAGES * STAGE_BYTES;           // 65536 B
    cudaFuncSetAttribute(gemm_mma, cudaFuncAttributeMaxDynamicSharedMemorySize,
                         gemm_smem);

    rope_table_kernel<<<(SEQN * 32 + 255) / 256, 256>>>();

    int n4x = MROWS * DIMM / 4;
    split_kernel<<<(n4x + 255) / 256, 256>>>(x, (__nv_bfloat16*)p_xhi,
                                             (__nv_bfloat16*)p_xlo, n4x);
    int n4w = DIMM * DIMM / 4;
    split_kernel<<<(n4w + 255) / 256, 256>>>(wq, (__nv_bfloat16*)p_wqhi,
                                             (__nv_bfloat16*)p_wqlo, n4w);
    split_kernel<<<(n4w + 255) / 256, 256>>>(wkv, (__nv_bfloat16*)p_wkhi,
                                             (__nv_bfloat16*)p_wklo, n4w);

    gemm_mma<<<dim3(MROWS / 128, DIMM / 128), 256, gemm_smem>>>(0);       // kv
    gemm_mma<<<dim3(BATCH * LAT / 128, DIMM / 128), 256, gemm_smem>>>(1); // q

    attn_split_kernel<<<dim3(BATCH * NHEAD, NSPLIT), 256, attn_smem>>>(lng, lnb);
    combine_kernel<<<BATCH * NHEAD, 256>>>(out);
}